// round 12
// baseline (speedup 1.0000x reference)
#include <cuda_runtime.h>
#include <math.h>

#define RPB  10
#define NT   320
#define PL   132
#define ROWF 1188          /* 9 planes * 132 */
#define RS_MUL 0.08838834764831845f

typedef unsigned long long u64;

__device__ float g_coef[11 * 125];

/* ---------------- W3J init (fp64, replicates reference; proven R6) ------- */
__device__ double dfact(int n) { double r = 1; for (int i = 2; i <= n; i++) r *= i; return r; }

__device__ double cg_d(int j1, int m1, int j2, int m2, int j3, int m3) {
    if (m1 + m2 != m3) return 0.0;
    double pre = sqrt((2.0 * j3 + 1.0) * dfact(j3 + j1 - j2) * dfact(j3 - j1 + j2) *
                      dfact(j1 + j2 - j3) / dfact(j1 + j2 + j3 + 1));
    pre *= sqrt(dfact(j3 + m3) * dfact(j3 - m3) * dfact(j1 - m1) * dfact(j1 + m1) *
                dfact(j2 - m2) * dfact(j2 + m2));
    double s = 0;
    for (int k = 0; k <= j1 + j2 - j3; k++) {
        int d0 = k, d1 = j1 + j2 - j3 - k, d2 = j1 - m1 - k;
        int d3 = j2 + m2 - k, d4 = j3 - j2 + m1 + k, d5 = j3 - j1 - m2 + k;
        if (d0 < 0 || d1 < 0 || d2 < 0 || d3 < 0 || d4 < 0 || d5 < 0) continue;
        double den = dfact(d0) * dfact(d1) * dfact(d2) * dfact(d3) * dfact(d4) * dfact(d5);
        s += ((k & 1) ? -1.0 : 1.0) / den;
    }
    return pre * s;
}

__global__ void w3j_init() {
    __shared__ double Wc[125], Wr[125];
    __shared__ double Qr[3][25], Qi[3][25];
    __shared__ double s_sign;
    const int L1[11] = {0,0,0,1,1,1,1,2,2,2,2};
    const int L2[11] = {0,1,2,0,1,1,2,0,1,2,2};
    const int L3[11] = {0,1,2,1,0,2,1,2,1,0,2};
    const int NP[3] = {3, 4, 4};
    int ins = blockIdx.x;
    int l1 = L1[ins], l2 = L2[ins], l3 = L3[ins];
    int d1 = 2*l1+1, d2 = 2*l2+1, d3 = 2*l3+1;
    int t = threadIdx.x;
    int x = t / 25, y = (t / 5) % 5, z = t % 5;

    if (t == 0) {
        int ls[3] = {l1, l2, l3};
        for (int q = 0; q < 3; q++) {
            int l = ls[q];
            for (int a = 0; a < 25; a++) { Qr[q][a] = 0; Qi[q][a] = 0; }
            Qr[q][l*5 + l] = 1.0;
            double s = 1.0 / sqrt(2.0);
            for (int m = 1; m <= l; m++) {
                double sg = (m & 1) ? -1.0 : 1.0;
                Qr[q][(l+m)*5 + (l-m)] = s;
                Qr[q][(l+m)*5 + (l+m)] = sg * s;
                Qi[q][(l-m)*5 + (l-m)] = s;
                Qi[q][(l-m)*5 + (l+m)] = -sg * s;
            }
        }
    }
    double wc = 0;
    if (x < d1 && y < d2 && z < d3) {
        int m1 = x - l1, m2 = y - l2, m3 = z - l3;
        if (m3 == -(m1 + m2)) {
            int e = l1 - l2 - m3;
            double sg = (e & 1) ? -1.0 : 1.0;
            wc = sg / sqrt(2.0 * l3 + 1.0) * cg_d(l1, m1, l2, m2, l3, -m3);
        }
    }
    Wc[t] = wc;
    __syncthreads();

    double acc = 0;
    if (x < d1 && y < d2 && z < d3) {
        for (int a = 0; a < d1; a++)
            for (int b = 0; b < d2; b++) {
                double q1r = Qr[0][x*5+a], q1i = Qi[0][x*5+a];
                double q2r = Qr[1][y*5+b], q2i = Qi[1][y*5+b];
                double ur = q1r * q2r - q1i * q2i;
                double ui = q1r * q2i + q1i * q2r;
                for (int c = 0; c < d3; c++) {
                    double w = Wc[a*25 + b*5 + c];
                    if (w != 0.0) {
                        double re = ur * Qr[2][z*5+c] - ui * Qi[2][z*5+c];
                        acc += re * w;
                    }
                }
            }
    }
    Wr[t] = acc;
    __syncthreads();

    if (t == 0) {
        double amax = 0;
        for (int a = 0; a < d1; a++) for (int b = 0; b < d2; b++) for (int c = 0; c < d3; c++) {
            double av = fabs(Wr[a*25 + b*5 + c]);
            if (av > amax) amax = av;
        }
        double sg = 1.0; int done = 0;
        for (int a = 0; a < d1; a++) for (int b = 0; b < d2; b++) for (int c = 0; c < d3; c++) {
            double w = Wr[a*25 + b*5 + c];
            if (!done && fabs(w) >= amax * (1.0 - 1e-9)) { sg = (w >= 0) ? 1.0 : -1.0; done = 1; }
        }
        /* (2,2,2): mixed-sign max tie; numpy argmax lands on a negative
           element (verified empirically R5->R6). */
        if (ins == 10) sg = -sg;
        s_sign = sg;
    }
    __syncthreads();

    double pw = sqrt((2.0 * l3 + 1.0) / (double)NP[l3]);
    float o = 0.f;
    if (x < d1 && y < d2 && z < d3) o = (float)(Wr[t] * s_sign * pw);
    g_coef[ins * 125 + t] = o;
}

/* ---------------- f32x2 helpers ---------------- */
__device__ __forceinline__ u64 ffma2(u64 a, u64 b, u64 c) {
    u64 d;
    asm("fma.rn.f32x2 %0, %1, %2, %3;" : "=l"(d) : "l"(a), "l"(b), "l"(c));
    return d;
}
__device__ __forceinline__ float hadd2(u64 v) {
    float lo, hi;
    asm("mov.b64 {%0,%1}, %2;" : "=f"(lo), "=f"(hi) : "l"(v));
    return lo + hi;
}

/* ---------------- Main fused kernel ---------------- */
/* Stage weights pair-major: WT2[u2][v] = {w[2u2][v], w[2u2+1][v]} (float2),
   vectorized: 2 LDG.128 + 2 STS.128 per 8 elements. */
__device__ __forceinline__ void stage_w2(const float* __restrict__ gw, float* wt2, int t) {
    for (int flat = t; flat < 2048; flat += NT) {
        int u2 = flat >> 5;
        int v4 = (flat & 31) << 2;
        float4 g0 = *(const float4*)(gw + (2 * u2) * 128 + v4);
        float4 g1 = *(const float4*)(gw + (2 * u2 + 1) * 128 + v4);
        float* d = wt2 + (u2 * 128 + v4) * 2;
        *(float4*)(d)     = make_float4(g0.x, g1.x, g0.y, g1.y);
        *(float4*)(d + 4) = make_float4(g0.z, g1.z, g0.w, g1.w);
    }
}

/* warp w: rowpair rp = w%5 (rows 2rp,2rp+1), kslice ks = w/5 (u in [64ks,64ks+64)).
   lane computes v = lane + 32c, c = 0..3. ks1 writes raw partial to outb;
   after sync ks0 adds its partial, applies RS_MUL + bias, writes final. */
template <int DIM>
__device__ __forceinline__ void gemm2(const float* __restrict__ inb, float* __restrict__ outb,
                                      const float* __restrict__ wt2,
                                      const float* __restrict__ bias,
                                      int lane, int rp, int ks, int loff) {
    u64 acc[2][4][DIM];
#pragma unroll
    for (int rr = 0; rr < 2; rr++)
#pragma unroll
        for (int c = 0; c < 4; c++)
#pragma unroll
            for (int i = 0; i < DIM; i++) acc[rr][c][i] = 0ull;

    const float* a0 = inb + (2 * rp) * ROWF + loff;
    int ub = ks * 64;
#pragma unroll 4
    for (int u = ub; u < ub + 64; u += 4) {
        ulonglong2 a[2][DIM];                 /* one LDS.128 broadcast per (rr,i) */
#pragma unroll
        for (int rr = 0; rr < 2; rr++)
#pragma unroll
            for (int i = 0; i < DIM; i++)
                a[rr][i] = *(const ulonglong2*)(a0 + rr * ROWF + i * PL + u);
        u64 w[2][4];
#pragma unroll
        for (int p = 0; p < 2; p++)
#pragma unroll
            for (int c = 0; c < 4; c++)
                w[p][c] = *(const u64*)(wt2 + (((u >> 1) + p) * 128 + lane + 32 * c) * 2);
#pragma unroll
        for (int rr = 0; rr < 2; rr++)
#pragma unroll
            for (int c = 0; c < 4; c++)
#pragma unroll
                for (int i = 0; i < DIM; i++) {
                    acc[rr][c][i] = ffma2(a[rr][i].x, w[0][c], acc[rr][c][i]);
                    acc[rr][c][i] = ffma2(a[rr][i].y, w[1][c], acc[rr][c][i]);
                }
    }

    if (ks == 1) {
#pragma unroll
        for (int rr = 0; rr < 2; rr++)
#pragma unroll
            for (int c = 0; c < 4; c++)
#pragma unroll
                for (int i = 0; i < DIM; i++)
                    outb[(2 * rp + rr) * ROWF + loff + i * PL + lane + 32 * c] = hadd2(acc[rr][c][i]);
    }
    __syncthreads();
    if (ks == 0) {
#pragma unroll
        for (int c = 0; c < 4; c++) {
            int v = lane + 32 * c;
            float bv = bias ? bias[v] : 0.f;
#pragma unroll
            for (int rr = 0; rr < 2; rr++)
#pragma unroll
                for (int i = 0; i < DIM; i++) {
                    int idx = (2 * rp + rr) * ROWF + loff + i * PL + v;
                    float s = hadd2(acc[rr][c][i]) + outb[idx];
                    outb[idx] = s * RS_MUL + bv;
                }
        }
    }
}

#define TP_INS(n, D1, D2, D3, B1, B2, B3)                                   \
    do {                                                                    \
        float w_ = TW[(n)*128 + u];                                         \
        _Pragma("unroll") for (int xx = 0; xx < (D1); xx++)                 \
        _Pragma("unroll") for (int yy = 0; yy < (D2); yy++) {               \
            float t2 = w_ * cl[(B1) + xx] * cr[(B2) + yy];                  \
            _Pragma("unroll") for (int zz = 0; zz < (D3); zz++)             \
                o[(B3) + zz] = fmaf(t2, CF[(n)*125 + xx*25 + yy*5 + zz],    \
                                    o[(B3) + zz]);                          \
        }                                                                   \
    } while (0)

__global__ void __launch_bounds__(NT, 1)
self_layer_kernel(const float* __restrict__ x, const float* __restrict__ oldf,
                  const float* __restrict__ wl, const float* __restrict__ bl,
                  const float* __restrict__ wr, const float* __restrict__ br,
                  const float* __restrict__ wp, const float* __restrict__ bp,
                  const float* __restrict__ tpw, const float* __restrict__ lnw,
                  const float* __restrict__ lnb, float* __restrict__ out, int N) {
    extern __shared__ float sm[];
    float* A  = sm;                  /* 10*1188 */
    float* Bf = A + RPB * ROWF;
    float* Cf = Bf + RPB * ROWF;
    float* WT = Cf + RPB * ROWF;     /* 16384 : pair-major weights */
    float* CF = WT + 16384;          /* 1375 */
    float* TW = CF + 1375;           /* 1408 */
    float* RS = TW + 1408;           /* 40 */

    int t = threadIdx.x;
    int n0 = blockIdx.x * RPB;

    /* load x -> planar A: jj-outer (mapping computed once), r-inner */
    for (int jj = t; jj < 1152; jj += NT) {
        int p, u;
        if (jj < 128)      { p = 0; u = jj; }
        else if (jj < 512) { int q = jj - 128; u = q / 3; p = 1 + (q - u * 3); }
        else               { int q = jj - 512; u = q / 5; p = 4 + (q - u * 5); }
        const float* xs = x + (size_t)n0 * 1152 + jj;
        float* as = A + p * PL + u;
#pragma unroll 1
        for (int r = 0; r < RPB; r++) {
            int n = n0 + r;
            as[r * ROWF] = (n < N) ? xs[(size_t)r * 1152] : 0.f;
        }
    }
    for (int i = t; i < 1375; i += NT) CF[i] = g_coef[i];
    for (int i = t; i < 1408; i += NT) TW[i] = tpw[i];
    __syncthreads();

    int lane = t & 31, w = t >> 5;
    int rp = w % 5, ks = w / 5;

    /* lin_l : A -> Bf */
    stage_w2(wl,         WT, t); __syncthreads(); gemm2<1>(A, Bf, WT, bl, lane, rp, ks, 0);      __syncthreads();
    stage_w2(wl + 16384, WT, t); __syncthreads(); gemm2<3>(A, Bf, WT, 0,  lane, rp, ks, PL);     __syncthreads();
    stage_w2(wl + 32768, WT, t); __syncthreads(); gemm2<5>(A, Bf, WT, 0,  lane, rp, ks, 4 * PL); __syncthreads();
    /* lin_r : A -> Cf */
    stage_w2(wr,         WT, t); __syncthreads(); gemm2<1>(A, Cf, WT, br, lane, rp, ks, 0);      __syncthreads();
    stage_w2(wr + 16384, WT, t); __syncthreads(); gemm2<3>(A, Cf, WT, 0,  lane, rp, ks, PL);     __syncthreads();
    stage_w2(wr + 32768, WT, t); __syncthreads(); gemm2<5>(A, Cf, WT, 0,  lane, rp, ks, 4 * PL); __syncthreads();

    /* tensor product: Bf,Cf -> A  (10*128 = 1280 items, 4 passes exactly) */
#pragma unroll 1
    for (int it = 0; it < 4; ++it) {
        int idx = it * NT + t;
        int r = idx >> 7, u = idx & 127;
        int base = r * ROWF + u;
        float cl[9], cr[9], o[9];
#pragma unroll
        for (int c = 0; c < 9; c++) { cl[c] = Bf[base + c * PL]; cr[c] = Cf[base + c * PL]; o[c] = 0.f; }
        TP_INS(0, 1, 1, 1, 0, 0, 0);
        TP_INS(1, 1, 3, 3, 0, 1, 1);
        TP_INS(2, 1, 5, 5, 0, 4, 4);
        TP_INS(3, 3, 1, 3, 1, 0, 1);
        TP_INS(4, 3, 3, 1, 1, 1, 0);
        TP_INS(5, 3, 3, 5, 1, 1, 4);
        TP_INS(6, 3, 5, 3, 1, 4, 1);
        TP_INS(7, 5, 1, 5, 4, 0, 4);
        TP_INS(8, 5, 3, 3, 4, 1, 1);
        TP_INS(9, 5, 5, 1, 4, 4, 0);
        TP_INS(10, 5, 5, 5, 4, 4, 4);
#pragma unroll
        for (int c = 0; c < 9; c++) A[base + c * PL] = o[c];
    }
    __syncthreads();

    /* lin_p : A -> Bf */
    stage_w2(wp,         WT, t); __syncthreads(); gemm2<1>(A, Bf, WT, bp, lane, rp, ks, 0);      __syncthreads();
    stage_w2(wp + 16384, WT, t); __syncthreads(); gemm2<3>(A, Bf, WT, 0,  lane, rp, ks, PL);     __syncthreads();
    stage_w2(wp + 32768, WT, t); __syncthreads(); gemm2<5>(A, Bf, WT, 0,  lane, rp, ks, 4 * PL); __syncthreads();

    /* e3norm stats: one warp per row (10 warps, 10 rows) */
    {
        int r = w;
        const float* fr = Bf + r * ROWF;
        float s0 = 0, q0 = 0, q1 = 0, q2 = 0;
        {
            float4 a = *(const float4*)(fr + lane * 4);
            s0 = a.x + a.y + a.z + a.w;
            q0 = a.x * a.x + a.y * a.y + a.z * a.z + a.w * a.w;
        }
#pragma unroll
        for (int p = 1; p < 4; p++) {
            float4 a = *(const float4*)(fr + p * PL + lane * 4);
            q1 += a.x * a.x + a.y * a.y + a.z * a.z + a.w * a.w;
        }
#pragma unroll
        for (int p = 4; p < 9; p++) {
            float4 a = *(const float4*)(fr + p * PL + lane * 4);
            q2 += a.x * a.x + a.y * a.y + a.z * a.z + a.w * a.w;
        }
#pragma unroll
        for (int off = 16; off; off >>= 1) {
            s0 += __shfl_xor_sync(0xffffffffu, s0, off);
            q0 += __shfl_xor_sync(0xffffffffu, q0, off);
            q1 += __shfl_xor_sync(0xffffffffu, q1, off);
            q2 += __shfl_xor_sync(0xffffffffu, q2, off);
        }
        if (lane == 0) {
            float mean = s0 * (1.f / 128.f);
            RS[r * 4 + 0] = mean;
            RS[r * 4 + 1] = rsqrtf(q0 * (1.f / 128.f) - mean * mean + 1e-5f);
            RS[r * 4 + 2] = rsqrtf(q1 * (1.f / 384.f) + 1e-5f);
            RS[r * 4 + 3] = rsqrtf(q2 * (1.f / 640.f) + 1e-5f);
        }
    }
    __syncthreads();

    /* scale + bias + residual -> out: jj-outer (mapping hoisted), r-inner */
    for (int jj = t; jj < 1152; jj += NT) {
        int p, u, l;
        if (jj < 128)      { l = 0; p = 0; u = jj; }
        else if (jj < 512) { l = 1; int q = jj - 128; u = q / 3; p = 1 + (q - u * 3); }
        else               { l = 2; int q = jj - 512; u = q / 5; p = 4 + (q - u * 5); }
        float lw = lnw[l * 128 + u];
        float lb = (l == 0) ? lnb[u] : 0.f;
        const float* bs = Bf + p * PL + u;
        const float* os = oldf + (size_t)n0 * 1152 + jj;
        float* ds = out + (size_t)n0 * 1152 + jj;
#pragma unroll 1
        for (int r = 0; r < RPB; r++) {
            int n = n0 + r;
            if (n >= N) break;
            float val = bs[r * ROWF];
            if (l == 0)      val = (val - RS[r * 4]) * RS[r * 4 + 1] * lw + lb;
            else if (l == 1) val = val * RS[r * 4 + 2] * lw;
            else             val = val * RS[r * 4 + 3] * lw;
            ds[(size_t)r * 1152] = val + os[(size_t)r * 1152];
        }
    }
}

extern "C" void kernel_launch(void* const* d_in, const int* in_sizes, int n_in,
                              void* d_out, int out_size) {
    const float* x    = (const float*)d_in[0];
    const float* oldf = (const float*)d_in[1];
    const float* wl   = (const float*)d_in[2];
    const float* bl   = (const float*)d_in[3];
    const float* wr   = (const float*)d_in[4];
    const float* br   = (const float*)d_in[5];
    const float* wp   = (const float*)d_in[6];
    const float* bp   = (const float*)d_in[7];
    const float* tpw  = (const float*)d_in[8];
    const float* lnw  = (const float*)d_in[9];
    const float* lnb  = (const float*)d_in[10];
    float* out = (float*)d_out;
    int N = in_sizes[0] / 1152;

    w3j_init<<<11, 125>>>();

    size_t smem = (size_t)(3 * RPB * ROWF + 16384 + 1375 + 1408 + 40) * sizeof(float);
    cudaFuncSetAttribute(self_layer_kernel, cudaFuncAttributeMaxDynamicSharedMemorySize, (int)smem);
    int blocks = (N + RPB - 1) / RPB;
    self_layer_kernel<<<blocks, NT, smem>>>(x, oldf, wl, bl, wr, br, wp, bp, tpw, lnw, lnb, out, N);
}

// round 15
// speedup vs baseline: 1.8556x; 1.8556x over previous
#include <cuda_runtime.h>
#include <math.h>

#define RS_MUL 0.08838834764831845f
typedef unsigned long long u64;

__device__ float g_coef[11 * 125];
__device__ float g_P[57600000];   /* planar scratch: x-planar, then xtp */
__device__ float g_R[57600000];   /* xr, then fii-planar */

/* ---------------- W3J init (fp64, replicates reference; proven R6) ------- */
__device__ double dfact(int n) { double r = 1; for (int i = 2; i <= n; i++) r *= i; return r; }

__device__ double cg_d(int j1, int m1, int j2, int m2, int j3, int m3) {
    if (m1 + m2 != m3) return 0.0;
    double pre = sqrt((2.0 * j3 + 1.0) * dfact(j3 + j1 - j2) * dfact(j3 - j1 + j2) *
                      dfact(j1 + j2 - j3) / dfact(j1 + j2 + j3 + 1));
    pre *= sqrt(dfact(j3 + m3) * dfact(j3 - m3) * dfact(j1 - m1) * dfact(j1 + m1) *
                dfact(j2 - m2) * dfact(j2 + m2));
    double s = 0;
    for (int k = 0; k <= j1 + j2 - j3; k++) {
        int d0 = k, d1 = j1 + j2 - j3 - k, d2 = j1 - m1 - k;
        int d3 = j2 + m2 - k, d4 = j3 - j2 + m1 + k, d5 = j3 - j1 - m2 + k;
        if (d0 < 0 || d1 < 0 || d2 < 0 || d3 < 0 || d4 < 0 || d5 < 0) continue;
        double den = dfact(d0) * dfact(d1) * dfact(d2) * dfact(d3) * dfact(d4) * dfact(d5);
        s += ((k & 1) ? -1.0 : 1.0) / den;
    }
    return pre * s;
}

__global__ void w3j_init() {
    __shared__ double Wc[125], Wr[125];
    __shared__ double Qr[3][25], Qi[3][25];
    __shared__ double s_sign;
    const int L1[11] = {0,0,0,1,1,1,1,2,2,2,2};
    const int L2[11] = {0,1,2,0,1,1,2,0,1,2,2};
    const int L3[11] = {0,1,2,1,0,2,1,2,1,0,2};
    const int NP[3] = {3, 4, 4};
    int ins = blockIdx.x;
    int l1 = L1[ins], l2 = L2[ins], l3 = L3[ins];
    int d1 = 2*l1+1, d2 = 2*l2+1, d3 = 2*l3+1;
    int t = threadIdx.x;
    int x = t / 25, y = (t / 5) % 5, z = t % 5;

    if (t == 0) {
        int ls[3] = {l1, l2, l3};
        for (int q = 0; q < 3; q++) {
            int l = ls[q];
            for (int a = 0; a < 25; a++) { Qr[q][a] = 0; Qi[q][a] = 0; }
            Qr[q][l*5 + l] = 1.0;
            double s = 1.0 / sqrt(2.0);
            for (int m = 1; m <= l; m++) {
                double sg = (m & 1) ? -1.0 : 1.0;
                Qr[q][(l+m)*5 + (l-m)] = s;
                Qr[q][(l+m)*5 + (l+m)] = sg * s;
                Qi[q][(l-m)*5 + (l-m)] = s;
                Qi[q][(l-m)*5 + (l+m)] = -sg * s;
            }
        }
    }
    double wc = 0;
    if (x < d1 && y < d2 && z < d3) {
        int m1 = x - l1, m2 = y - l2, m3 = z - l3;
        if (m3 == -(m1 + m2)) {
            int e = l1 - l2 - m3;
            double sg = (e & 1) ? -1.0 : 1.0;
            wc = sg / sqrt(2.0 * l3 + 1.0) * cg_d(l1, m1, l2, m2, l3, -m3);
        }
    }
    Wc[t] = wc;
    __syncthreads();

    double acc = 0;
    if (x < d1 && y < d2 && z < d3) {
        for (int a = 0; a < d1; a++)
            for (int b = 0; b < d2; b++) {
                double q1r = Qr[0][x*5+a], q1i = Qi[0][x*5+a];
                double q2r = Qr[1][y*5+b], q2i = Qi[1][y*5+b];
                double ur = q1r * q2r - q1i * q2i;
                double ui = q1r * q2i + q1i * q2r;
                for (int c = 0; c < d3; c++) {
                    double w = Wc[a*25 + b*5 + c];
                    if (w != 0.0) {
                        double re = ur * Qr[2][z*5+c] - ui * Qi[2][z*5+c];
                        acc += re * w;
                    }
                }
            }
    }
    Wr[t] = acc;
    __syncthreads();

    if (t == 0) {
        double amax = 0;
        for (int a = 0; a < d1; a++) for (int b = 0; b < d2; b++) for (int c = 0; c < d3; c++) {
            double av = fabs(Wr[a*25 + b*5 + c]);
            if (av > amax) amax = av;
        }
        double sg = 1.0; int done = 0;
        for (int a = 0; a < d1; a++) for (int b = 0; b < d2; b++) for (int c = 0; c < d3; c++) {
            double w = Wr[a*25 + b*5 + c];
            if (!done && fabs(w) >= amax * (1.0 - 1e-9)) { sg = (w >= 0) ? 1.0 : -1.0; done = 1; }
        }
        if (ins == 10) sg = -sg;   /* proven R5->R6 */
        s_sign = sg;
    }
    __syncthreads();

    double pw = sqrt((2.0 * l3 + 1.0) / (double)NP[l3]);
    float o = 0.f;
    if (x < d1 && y < d2 && z < d3) o = (float)(Wr[t] * s_sign * pw);
    g_coef[ins * 125 + t] = o;
}

/* ---------------- f32x2 helpers ---------------- */
__device__ __forceinline__ u64 ffma2(u64 a, u64 b, u64 c) {
    u64 d;
    asm("fma.rn.f32x2 %0, %1, %2, %3;" : "=l"(d) : "l"(a), "l"(b), "l"(c));
    return d;
}
__device__ __forceinline__ u64 dup2(float v) {
    u64 d;
    asm("mov.b64 %0, {%1, %1};" : "=l"(d) : "f"(v));
    return d;
}
__device__ __forceinline__ float lo32(u64 v) { return __uint_as_float((unsigned)v); }
__device__ __forceinline__ float hi32(u64 v) { return __uint_as_float((unsigned)(v >> 32)); }

/* ---------------- K1: reorder x flat -> planar ---------------- */
__global__ void __launch_bounds__(256, 2)
reorder_kernel(const float* __restrict__ x, int N) {
    __shared__ float S[8][1152];
    int t = threadIdx.x;
    int n0 = blockIdx.x * 8;
    for (int idx = t; idx < 8 * 1152; idx += 256) {
        int r = idx / 1152, jj = idx - r * 1152;
        int n = n0 + r;
        float val = (n < N) ? x[(size_t)n * 1152 + jj] : 0.f;
        int p, u;
        if (jj < 128)      { p = 0; u = jj; }
        else if (jj < 512) { int q = jj - 128; u = q / 3; p = 1 + (q - u * 3); }
        else               { int q = jj - 512; u = q / 5; p = 4 + (q - u * 5); }
        S[r][p * 128 + u] = val;
    }
    __syncthreads();
    for (int idx = t; idx < 8 * 1152; idx += 256) {
        int r = idx / 1152, pp = idx - r * 1152;
        int n = n0 + r;
        if (n < N) g_P[(size_t)n * 1152 + pp] = S[r][pp];
    }
}

/* ---------------- GEMM: C[m,v] = (sum_u A[m,u] W[u,v]) * RS_MUL (+bias l0)
   A planar rows; per-l segments in blockIdx.x. BM=128, BN=128, BK=16. -------- */
__global__ void __launch_bounds__(256, 2)
gemm_lin(const float* __restrict__ P, const float* __restrict__ Wb,
         const float* __restrict__ bias, float* __restrict__ Out,
         int N, int t0, int t1) {
    __shared__ __align__(16) float As[2][16][132];
    __shared__ __align__(16) float Bs[2][16][128];
    int b = blockIdx.x, l, mt;
    if (b < t0) { l = 0; mt = b; }
    else if (b < t0 + t1) { l = 1; mt = b - t0; }
    else { l = 2; mt = b - t0 - t1; }
    int d = 2 * l + 1, pb = l * l;
    int Ml = N * d;
    const float* W = Wb + l * 16384;

    int tid = threadIdx.x;
    /* A staging: thread -> (row ma, k-half) */
    int ma = tid >> 1, k8 = (tid & 1) << 3;
    int m_s = mt * 128 + ma;
    if (m_s >= Ml) m_s = Ml - 1;           /* clamp; value unused via av */
    int nn = m_s / d, ii = m_s - nn * d;
    const float* arow = P + (size_t)nn * 1152 + (pb + ii) * 128;
    bool av = (mt * 128 + ma) < Ml;
    /* B staging: thread -> (k row kb, v8) */
    int kb = tid >> 4, v8 = (tid & 15) << 3;

    float4 a0, a1, b0, b1;
    a0 = av ? *(const float4*)(arow + k8)     : make_float4(0,0,0,0);
    a1 = av ? *(const float4*)(arow + k8 + 4) : make_float4(0,0,0,0);
    b0 = *(const float4*)(W + kb * 128 + v8);
    b1 = *(const float4*)(W + kb * 128 + v8 + 4);
    {
        float av8[8] = {a0.x,a0.y,a0.z,a0.w,a1.x,a1.y,a1.z,a1.w};
#pragma unroll
        for (int j = 0; j < 8; j++) As[0][k8 + j][ma] = av8[j];
        *(float4*)&Bs[0][kb][v8]     = b0;
        *(float4*)&Bs[0][kb][v8 + 4] = b1;
    }
    __syncthreads();

    int tn = tid & 15, tm = tid >> 4;
    int m0 = tm * 8, n0c = tn * 8;
    u64 acc[4][8];
#pragma unroll
    for (int p = 0; p < 4; p++)
#pragma unroll
        for (int j = 0; j < 8; j++) acc[p][j] = 0ull;

#pragma unroll 1
    for (int kk = 0; kk < 8; kk++) {
        int buf = kk & 1;
        if (kk < 7) {
            int k0 = (kk + 1) * 16;
            a0 = av ? *(const float4*)(arow + k0 + k8)     : make_float4(0,0,0,0);
            a1 = av ? *(const float4*)(arow + k0 + k8 + 4) : make_float4(0,0,0,0);
            b0 = *(const float4*)(W + (k0 + kb) * 128 + v8);
            b1 = *(const float4*)(W + (k0 + kb) * 128 + v8 + 4);
        }
#pragma unroll
        for (int k = 0; k < 16; k++) {
            ulonglong2 A01 = *(const ulonglong2*)&As[buf][k][m0];
            ulonglong2 A23 = *(const ulonglong2*)&As[buf][k][m0 + 4];
            float4 bb0 = *(const float4*)&Bs[buf][k][n0c];
            float4 bb1 = *(const float4*)&Bs[buf][k][n0c + 4];
            float bf[8] = {bb0.x,bb0.y,bb0.z,bb0.w,bb1.x,bb1.y,bb1.z,bb1.w};
#pragma unroll
            for (int j = 0; j < 8; j++) {
                u64 bd = dup2(bf[j]);
                acc[0][j] = ffma2(A01.x, bd, acc[0][j]);
                acc[1][j] = ffma2(A01.y, bd, acc[1][j]);
                acc[2][j] = ffma2(A23.x, bd, acc[2][j]);
                acc[3][j] = ffma2(A23.y, bd, acc[3][j]);
            }
        }
        if (kk < 7) {
            int nb = buf ^ 1;
            float av8[8] = {a0.x,a0.y,a0.z,a0.w,a1.x,a1.y,a1.z,a1.w};
#pragma unroll
            for (int j = 0; j < 8; j++) As[nb][k8 + j][ma] = av8[j];
            *(float4*)&Bs[nb][kb][v8]     = b0;
            *(float4*)&Bs[nb][kb][v8 + 4] = b1;
        }
        __syncthreads();
    }

    /* epilogue */
    float bvv[8];
#pragma unroll
    for (int j = 0; j < 8; j++) bvv[j] = (l == 0) ? bias[n0c + j] : 0.f;
#pragma unroll
    for (int p = 0; p < 4; p++)
#pragma unroll
        for (int h = 0; h < 2; h++) {
            int m = mt * 128 + m0 + 2 * p + h;
            if (m < Ml) {
                int n_ = m / d, i_ = m - n_ * d;
                float* crow = Out + (size_t)n_ * 1152 + (pb + i_) * 128 + n0c;
                float4 o0, o1;
                o0.x = (h ? hi32(acc[p][0]) : lo32(acc[p][0])) * RS_MUL + bvv[0];
                o0.y = (h ? hi32(acc[p][1]) : lo32(acc[p][1])) * RS_MUL + bvv[1];
                o0.z = (h ? hi32(acc[p][2]) : lo32(acc[p][2])) * RS_MUL + bvv[2];
                o0.w = (h ? hi32(acc[p][3]) : lo32(acc[p][3])) * RS_MUL + bvv[3];
                o1.x = (h ? hi32(acc[p][4]) : lo32(acc[p][4])) * RS_MUL + bvv[4];
                o1.y = (h ? hi32(acc[p][5]) : lo32(acc[p][5])) * RS_MUL + bvv[5];
                o1.z = (h ? hi32(acc[p][6]) : lo32(acc[p][6])) * RS_MUL + bvv[6];
                o1.w = (h ? hi32(acc[p][7]) : lo32(acc[p][7])) * RS_MUL + bvv[7];
                *(float4*)(crow)     = o0;
                *(float4*)(crow + 4) = o1;
            }
        }
}

/* ---------------- K5: tensor product (planar xl=d_out, xr=g_R -> g_P) ----- */
#define TP_INS(n, D1, D2, D3, B1, B2, B3)                                   \
    do {                                                                    \
        float w_ = tpw[(n)*128 + u];                                        \
        _Pragma("unroll") for (int xx = 0; xx < (D1); xx++)                 \
        _Pragma("unroll") for (int yy = 0; yy < (D2); yy++) {               \
            float t2 = w_ * cl[(B1) + xx] * cr[(B2) + yy];                  \
            _Pragma("unroll") for (int zz = 0; zz < (D3); zz++)             \
                o[(B3) + zz] = fmaf(t2, CF[(n)*125 + xx*25 + yy*5 + zz],    \
                                    o[(B3) + zz]);                          \
        }                                                                   \
    } while (0)

__global__ void __launch_bounds__(256, 2)
tp_kernel(const float* __restrict__ xl, const float* __restrict__ tpw, int N) {
    __shared__ float CF[1375];
    int t = threadIdx.x;
    for (int i = t; i < 1375; i += 256) CF[i] = g_coef[i];
    __syncthreads();
    int g = blockIdx.x * 256 + t;
    if (g >= N * 128) return;
    int n = g >> 7, u = g & 127;
    size_t base = (size_t)n * 1152 + u;
    float cl[9], cr[9], o[9];
#pragma unroll
    for (int c = 0; c < 9; c++) { cl[c] = xl[base + c * 128]; cr[c] = g_R[base + c * 128]; o[c] = 0.f; }
    TP_INS(0, 1, 1, 1, 0, 0, 0);
    TP_INS(1, 1, 3, 3, 0, 1, 1);
    TP_INS(2, 1, 5, 5, 0, 4, 4);
    TP_INS(3, 3, 1, 3, 1, 0, 1);
    TP_INS(4, 3, 3, 1, 1, 1, 0);
    TP_INS(5, 3, 3, 5, 1, 1, 4);
    TP_INS(6, 3, 5, 3, 1, 4, 1);
    TP_INS(7, 5, 1, 5, 4, 0, 4);
    TP_INS(8, 5, 3, 3, 4, 1, 1);
    TP_INS(9, 5, 5, 1, 4, 4, 0);
    TP_INS(10, 5, 5, 5, 4, 4, 4);
#pragma unroll
    for (int c = 0; c < 9; c++) g_P[base + c * 128] = o[c];
}

/* ---------------- K6: e3norm + residual (fii planar in g_R -> out flat) --- */
__global__ void __launch_bounds__(256, 2)
norm_kernel(const float* __restrict__ fiiP, float* __restrict__ out,
            const float* __restrict__ oldf,
            const float* __restrict__ lnw, const float* __restrict__ lnb, int N) {
    int t = threadIdx.x, wid = t >> 5, lane = t & 31;
    int n = blockIdx.x * 8 + wid;
    if (n >= N) return;
    const float* fr = fiiP + (size_t)n * 1152;
    float s0 = 0, q0 = 0, q1 = 0, q2 = 0;
    {
        float4 a = *(const float4*)(fr + lane * 4);
        s0 = a.x + a.y + a.z + a.w;
        q0 = a.x * a.x + a.y * a.y + a.z * a.z + a.w * a.w;
    }
#pragma unroll
    for (int p = 1; p < 4; p++) {
        float4 a = *(const float4*)(fr + p * 128 + lane * 4);
        q1 += a.x * a.x + a.y * a.y + a.z * a.z + a.w * a.w;
    }
#pragma unroll
    for (int p = 4; p < 9; p++) {
        float4 a = *(const float4*)(fr + p * 128 + lane * 4);
        q2 += a.x * a.x + a.y * a.y + a.z * a.z + a.w * a.w;
    }
#pragma unroll
    for (int off = 16; off; off >>= 1) {
        s0 += __shfl_xor_sync(0xffffffffu, s0, off);
        q0 += __shfl_xor_sync(0xffffffffu, q0, off);
        q1 += __shfl_xor_sync(0xffffffffu, q1, off);
        q2 += __shfl_xor_sync(0xffffffffu, q2, off);
    }
    float mean = s0 * (1.f / 128.f);
    float inv0 = rsqrtf(q0 * (1.f / 128.f) - mean * mean + 1e-5f);
    float inv1 = rsqrtf(q1 * (1.f / 384.f) + 1e-5f);
    float inv2 = rsqrtf(q2 * (1.f / 640.f) + 1e-5f);

    float* dst = out + (size_t)n * 1152;
    const float* os = oldf + (size_t)n * 1152;
    for (int jj = lane; jj < 1152; jj += 32) {
        int p, u, l;
        if (jj < 128)      { l = 0; p = 0; u = jj; }
        else if (jj < 512) { l = 1; int q = jj - 128; u = q / 3; p = 1 + (q - u * 3); }
        else               { l = 2; int q = jj - 512; u = q / 5; p = 4 + (q - u * 5); }
        float val = fr[p * 128 + u];
        if (l == 0)      val = (val - mean) * inv0 * lnw[u] + lnb[u];
        else if (l == 1) val = val * inv1 * lnw[128 + u];
        else             val = val * inv2 * lnw[256 + u];
        dst[jj] = val + os[jj];
    }
}

extern "C" void kernel_launch(void* const* d_in, const int* in_sizes, int n_in,
                              void* d_out, int out_size) {
    const float* x    = (const float*)d_in[0];
    const float* oldf = (const float*)d_in[1];
    const float* wl   = (const float*)d_in[2];
    const float* bl   = (const float*)d_in[3];
    const float* wr   = (const float*)d_in[4];
    const float* br   = (const float*)d_in[5];
    const float* wp   = (const float*)d_in[6];
    const float* bp   = (const float*)d_in[7];
    const float* tpw  = (const float*)d_in[8];
    const float* lnw  = (const float*)d_in[9];
    const float* lnb  = (const float*)d_in[10];
    float* out = (float*)d_out;
    int N = in_sizes[0] / 1152;

    float* Pp; cudaGetSymbolAddress((void**)&Pp, g_P);
    float* Rp; cudaGetSymbolAddress((void**)&Rp, g_R);

    w3j_init<<<11, 125>>>();
    reorder_kernel<<<(N + 7) / 8, 256>>>(x, N);

    int t0 = (N + 127) / 128, t1 = (3 * N + 127) / 128, t2 = (5 * N + 127) / 128;
    int gg = t0 + t1 + t2;

    gemm_lin<<<gg, 256>>>(Pp, wl, bl, out, N, t0, t1);      /* xl  -> d_out (planar) */
    gemm_lin<<<gg, 256>>>(Pp, wr, br, Rp,  N, t0, t1);      /* xr  -> g_R   (planar) */
    tp_kernel<<<(N * 128 + 255) / 256, 256>>>(out, tpw, N); /* xtp -> g_P   (planar) */
    gemm_lin<<<gg, 256>>>(Pp, wp, bp, Rp,  N, t0, t1);      /* fii -> g_R   (planar) */
    norm_kernel<<<(N + 7) / 8, 256>>>(Rp, out, oldf, lnw, lnb, N);
}